// round 4
// baseline (speedup 1.0000x reference)
#include <cuda_runtime.h>
#include <cuda_bf16.h>
#include <math.h>
#include <stdint.h>

#if defined(__CUDA_ARCH__) && defined(__CUDA_ARCH_FEAT_SM103_ALL)
#define HAS_TCGEN05 1
#else
#define HAS_TCGEN05 0
#endif

#define BS 8
#define LL 4800
#define D 256
#define H 8
#define DH 32
#define ROWS (BS*LL)   // 38400
#define BSTRIDE (LL*D) // per-batch elements

#define BM 128
#define BN 256
#define BK 64
#define A_HI 0
#define A_LO 16384
#define B_HI 32768
#define B_LO 65536
#define STAGE_BYTES 98304
#define SMEM_DYN (2*STAGE_BYTES + 1024)

#define ATOK 32        // tokens per attn block

// ---------------- scratch (device globals) ----------------
__device__ float g_q   [BS*LL*D];
__device__ float g_k   [BS*LL*D];
__device__ float g_v   [BS*LL*D];
__device__ float g_qp  [BS*LL*D];
__device__ float g_kp  [BS*LL*D];
__device__ float g_vp  [BS*LL*D];
__device__ float g_xmid[BS*LL*D];
__device__ float g_kv  [BS*H*DH*DH];
__device__ float g_ksum[BS*H*DH];

// bf16 hi/lo buffers
__device__ __nv_bfloat16 g_mhi[ROWS*D],   g_mlo[ROWS*D];    // msg / input conversions
__device__ __nv_bfloat16 g_hhi[ROWS*2*D], g_hlo[ROWS*2*D];  // hcat (pitch 512)
__device__ __nv_bfloat16 g_thi[ROWS*2*D], g_tlo[ROWS*2*D];  // relu(hcat@W1)

// transposed bf16 weights [N,K]
__device__ __nv_bfloat16 g_wqh[D*D],     g_wql[D*D];
__device__ __nv_bfloat16 g_wkh[D*D],     g_wkl[D*D];
__device__ __nv_bfloat16 g_wvh[D*D],     g_wvl[D*D];
__device__ __nv_bfloat16 g_wmh[D*D],     g_wml[D*D];
__device__ __nv_bfloat16 g_w1h[2*D*2*D], g_w1l[2*D*2*D];
__device__ __nv_bfloat16 g_w2h[D*2*D],   g_w2l[D*2*D];

// ---------------- helpers ----------------
__device__ __forceinline__ float phi(float x) { return x > 0.f ? x + 1.f : __expf(x); }
__device__ __forceinline__ uint32_t smem_u32(const void* p) {
    uint32_t a;
    asm("{ .reg .u64 t; cvta.to.shared.u64 t, %1; cvt.u32.u64 %0, t; }" : "=r"(a) : "l"(p));
    return a;
}
__device__ __forceinline__ void split_store(__nv_bfloat16* hi, __nv_bfloat16* lo,
                                            size_t idx, float v) {
    __nv_bfloat16 h = __float2bfloat16(v);
    hi[idx] = h;
    lo[idx] = __float2bfloat16(v - __bfloat162float(h));
}

#if HAS_TCGEN05
__device__ __forceinline__ void mbar_init(uint32_t a, uint32_t cnt) {
    asm volatile("mbarrier.init.shared.b64 [%0], %1;" :: "r"(a), "r"(cnt) : "memory");
}
__device__ __forceinline__ void mbar_wait(uint32_t a, uint32_t parity) {
    asm volatile(
        "{\n\t.reg .pred P;\n"
        "W_%=:\n\t"
        "mbarrier.try_wait.parity.acquire.cta.shared::cta.b64 P, [%0], %1, 0x989680;\n\t"
        "@!P bra W_%=;\n\t}"
        :: "r"(a), "r"(parity) : "memory");
}
__device__ __forceinline__ uint64_t make_desc(uint32_t addr) {
    const uint64_t base = (uint64_t(2) << 61) | (uint64_t(1) << 46)
                        | (uint64_t(64) << 32) | (uint64_t(1) << 16);
    return base | ((uint64_t)(addr >> 4) & 0x3FFF);
}
__device__ __forceinline__ void mma_f16_ss(uint32_t d, uint64_t a, uint64_t b,
                                           uint32_t idesc, uint32_t en) {
    asm volatile(
        "{\n\t.reg .pred p;\n\tsetp.ne.u32 p, %5, 0;\n\t"
        "tcgen05.mma.cta_group::1.kind::f16 [%0], %1, %2, %3, {%4, %4, %4, %4}, p;\n\t}"
        :: "r"(d), "l"(a), "l"(b), "r"(idesc), "r"(0u), "r"(en) : "memory");
}
__device__ __forceinline__ void tc_commit(uint32_t mbar) {
    asm volatile(
        "tcgen05.commit.cta_group::1.mbarrier::arrive::one.shared::cluster.b64 [%0];"
        :: "r"(mbar) : "memory");
}
__device__ __forceinline__ void ldtm32(uint32_t* r, uint32_t addr) {
    asm volatile(
        "tcgen05.ld.sync.aligned.32x32b.x32.b32 "
        "{%0, %1, %2, %3, %4, %5, %6, %7, "
        " %8, %9, %10, %11, %12, %13, %14, %15, "
        " %16, %17, %18, %19, %20, %21, %22, %23, "
        " %24, %25, %26, %27, %28, %29, %30, %31}, [%32];"
        : "=r"(r[0]),  "=r"(r[1]),  "=r"(r[2]),  "=r"(r[3]),
          "=r"(r[4]),  "=r"(r[5]),  "=r"(r[6]),  "=r"(r[7]),
          "=r"(r[8]),  "=r"(r[9]),  "=r"(r[10]), "=r"(r[11]),
          "=r"(r[12]), "=r"(r[13]), "=r"(r[14]), "=r"(r[15]),
          "=r"(r[16]), "=r"(r[17]), "=r"(r[18]), "=r"(r[19]),
          "=r"(r[20]), "=r"(r[21]), "=r"(r[22]), "=r"(r[23]),
          "=r"(r[24]), "=r"(r[25]), "=r"(r[26]), "=r"(r[27]),
          "=r"(r[28]), "=r"(r[29]), "=r"(r[30]), "=r"(r[31])
        : "r"(addr));
    asm volatile("tcgen05.wait::ld.sync.aligned;" ::: "memory");
}
#endif

// ---------------- convert kernels ----------------
__global__ void __launch_bounds__(256) aconv(const float4* __restrict__ a,
                                             __nv_bfloat162* __restrict__ hi,
                                             __nv_bfloat162* __restrict__ lo, int n4) {
    int i = blockIdx.x * 256 + threadIdx.x;
    if (i >= n4) return;
    float4 v = a[i];
    __nv_bfloat16 h0 = __float2bfloat16(v.x), h1 = __float2bfloat16(v.y);
    __nv_bfloat16 h2 = __float2bfloat16(v.z), h3 = __float2bfloat16(v.w);
    hi[2*i]   = __halves2bfloat162(h0, h1);
    hi[2*i+1] = __halves2bfloat162(h2, h3);
    lo[2*i]   = __halves2bfloat162(__float2bfloat16(v.x - __bfloat162float(h0)),
                                   __float2bfloat16(v.y - __bfloat162float(h1)));
    lo[2*i+1] = __halves2bfloat162(__float2bfloat16(v.z - __bfloat162float(h2)),
                                   __float2bfloat16(v.w - __bfloat162float(h3)));
}

__global__ void __launch_bounds__(256) wconv(const float* __restrict__ W,
                                             __nv_bfloat16* __restrict__ hi,
                                             __nv_bfloat16* __restrict__ lo,
                                             int K, int N) {
    int i = blockIdx.x * 256 + threadIdx.x;
    if (i >= N * K) return;
    int n = i / K, k = i % K;
    float v = W[(size_t)k * N + n];
    __nv_bfloat16 h = __float2bfloat16(v);
    hi[i] = h;
    lo[i] = __float2bfloat16(v - __bfloat162float(h));
}

// hcat xb half: hhi/hlo[row*512 + c] = split(xb[row*256+c])
__global__ void __launch_bounds__(256) hcat_base(const float4* __restrict__ xb,
                                                 __nv_bfloat16* __restrict__ hhi,
                                                 __nv_bfloat16* __restrict__ hlo) {
    int i = blockIdx.x * 256 + threadIdx.x;   // float4 index, ROWS*64 total
    if (i >= ROWS * 64) return;
    int row = i >> 6, j = i & 63;
    float4 v = xb[i];
    size_t o = (size_t)row * 512 + j * 4;
    split_store(hhi, hlo, o + 0, v.x);
    split_store(hhi, hlo, o + 1, v.y);
    split_store(hhi, hlo, o + 2, v.z);
    split_store(hhi, hlo, o + 3, v.w);
}

// ---------------- tcgen05 GEMM ----------------
// EPI 0: fp32 -> Cf (pitch ldc)
// EPI 1: relu -> bf16 hi/lo (pitch ldc, col offset bn)
// EPI 2: LN(g,b) -> bf16 hi/lo at pitch ldc, col offset coff (hcat LN half)
// EPI 3: Cf[row*ldc+col] += 0.5*LN(g,b)
__device__ __forceinline__ void load_stage(char* st,
        const __nv_bfloat16* __restrict__ Ahi, const __nv_bfloat16* __restrict__ Alo,
        const __nv_bfloat16* __restrict__ Bhi, const __nv_bfloat16* __restrict__ Blo,
        int bm, int bn, int k0, int K, int t) {
    #pragma unroll
    for (int it = 0; it < 4; it++) {
        int i = t + it * 256;
        int row = i >> 3, j = i & 7;
        uint32_t off = row * 128 + j * 16;
        uint32_t sw = off ^ ((off >> 3) & 0x70);
        size_t g = (size_t)(bm + row) * K + k0 + j * 8;
        *(uint4*)(st + A_HI + sw) = *(const uint4*)(Ahi + g);
        *(uint4*)(st + A_LO + sw) = *(const uint4*)(Alo + g);
    }
    #pragma unroll
    for (int it = 0; it < 8; it++) {
        int i = t + it * 256;
        int row = i >> 3, j = i & 7;
        uint32_t off = row * 128 + j * 16;
        uint32_t sw = off ^ ((off >> 3) & 0x70);
        size_t g = (size_t)(bn + row) * K + k0 + j * 8;
        *(uint4*)(st + B_HI + sw) = *(const uint4*)(Bhi + g);
        *(uint4*)(st + B_LO + sw) = *(const uint4*)(Blo + g);
    }
}

template<int EPI>
__global__ void __launch_bounds__(256, 1) tc_gemm(
        const __nv_bfloat16* __restrict__ Ahi, const __nv_bfloat16* __restrict__ Alo,
        const __nv_bfloat16* __restrict__ Bhi, const __nv_bfloat16* __restrict__ Blo,
        float* __restrict__ Cf,
        __nv_bfloat16* __restrict__ Chi, __nv_bfloat16* __restrict__ Clo,
        const float* __restrict__ Gw, const float* __restrict__ Bw,
        int K, int N, int ldc, int coff) {
#if HAS_TCGEN05
    extern __shared__ char dsm_raw[];
    char* sbase = (char*)(((uintptr_t)dsm_raw + 1023) & ~(uintptr_t)1023);
    __shared__ uint32_t s_tmem;
    __shared__ __align__(8) unsigned long long s_mbar[2];
    const uint32_t mb = smem_u32(s_mbar);
    const int t = threadIdx.x, wid = t >> 5, lane = t & 31;

    if (wid == 0) {
        asm volatile("tcgen05.alloc.cta_group::1.sync.aligned.shared::cta.b32 [%0], %1;"
                     :: "r"(smem_u32(&s_tmem)), "r"(256u) : "memory");
        asm volatile("tcgen05.relinquish_alloc_permit.cta_group::1.sync.aligned;");
    }
    if (t == 0) { mbar_init(mb, 1); mbar_init(mb + 8, 1); }
    __syncthreads();
    const uint32_t tmem = s_tmem;

    const int bm = blockIdx.y * BM, bn = blockIdx.x * BN;
    const int NC = K >> 6;
    const uint32_t idesc = (1u << 4) | (1u << 7) | (1u << 10)
                         | ((BN / 8) << 17) | ((BM / 16) << 24);

    load_stage(sbase, Ahi, Alo, Bhi, Blo, bm, bn, 0, K, t);
    asm volatile("fence.proxy.async.shared::cta;" ::: "memory");
    __syncthreads();

    int ph[2] = {0, 0};
    int pend[2] = {0, 0};
    const uint32_t sb32 = smem_u32(sbase);
    for (int c = 0; c < NC; c++) {
        const int s = c & 1;
        if (t == 0) {
            uint32_t st = sb32 + s * STAGE_BYTES;
            uint64_t dAh = make_desc(st + A_HI), dAl = make_desc(st + A_LO);
            uint64_t dBh = make_desc(st + B_HI), dBl = make_desc(st + B_LO);
            #pragma unroll
            for (int k = 0; k < 4; k++) {
                mma_f16_ss(tmem, dAh + k * 2, dBh + k * 2, idesc, !(c == 0 && k == 0));
                mma_f16_ss(tmem, dAh + k * 2, dBl + k * 2, idesc, 1u);
                mma_f16_ss(tmem, dAl + k * 2, dBh + k * 2, idesc, 1u);
            }
            tc_commit(mb + s * 8);
        }
        pend[s] = 1;
        if (c + 1 < NC) {
            const int s2 = (c + 1) & 1;
            if (pend[s2]) { mbar_wait(mb + s2 * 8, ph[s2]); ph[s2] ^= 1; pend[s2] = 0; }
            load_stage(sbase + s2 * STAGE_BYTES,
                       Ahi, Alo, Bhi, Blo, bm, bn, (c + 1) * BK, K, t);
            asm volatile("fence.proxy.async.shared::cta;" ::: "memory");
            __syncthreads();
        }
    }
    if (pend[0]) mbar_wait(mb,     ph[0]);
    if (pend[1]) mbar_wait(mb + 8, ph[1]);
    asm volatile("tcgen05.fence::after_thread_sync;" ::: "memory");
    __syncthreads();   // smem stages now free for epilogue reuse

    float (*tile)[33] = (float(*)[33])sbase;
    float mean = 0.f, rstd = 0.f;
    if (EPI >= 2 && wid < 4) {
        float s = 0.f, s2 = 0.f;
        #pragma unroll
        for (int ch = 0; ch < 8; ch++) {
            uint32_t r[32];
            ldtm32(r, tmem + ch * 32);
            #pragma unroll
            for (int j = 0; j < 32; j++) {
                float v = __uint_as_float(r[j]);
                s += v; s2 += v * v;
            }
        }
        mean = s * (1.f / 256.f);
        float var = fmaf(-mean, mean, s2 * (1.f / 256.f));
        rstd = rsqrtf(var + 1e-5f);
    }
    #pragma unroll
    for (int ch = 0; ch < 8; ch++) {
        if (wid < 4) {
            uint32_t r[32];
            ldtm32(r, tmem + ch * 32);
            int rloc = wid * 32 + lane;
            #pragma unroll
            for (int j = 0; j < 32; j++) {
                float v = __uint_as_float(r[j]);
                if (EPI == 1) v = fmaxf(v, 0.f);
                if (EPI >= 2) {
                    int col = ch * 32 + j;
                    v = (v - mean) * rstd * Gw[col] + Bw[col];
                    if (EPI == 3) v *= 0.5f;
                }
                tile[rloc][j] = v;
            }
        }
        __syncthreads();
        #pragma unroll
        for (int i = 0; i < 16; i++) {
            int idx = i * 256 + t;
            int rr = idx >> 5, cc = idx & 31;
            float v = tile[rr][cc];
            size_t ro = (size_t)(bm + rr) * ldc + bn + coff + ch * 32 + cc;
            if (EPI == 0)       Cf[ro] = v;
            else if (EPI == 3)  Cf[ro] += v;
            else                split_store(Chi, Clo, ro, v);
        }
        __syncthreads();
    }
    if (wid == 0)
        asm volatile("tcgen05.dealloc.cta_group::1.sync.aligned.b32 %0, %1;"
                     :: "r"(tmem), "r"(256u));
#else
    // compile-only fallback for the non-103a pass (never runs on GB300)
    const int bm = blockIdx.y * BM, bn = blockIdx.x * BN;
    const int t = threadIdx.x;
    if (t < BM) {
        int row = bm + t;
        float vals[BN];
        for (int c = 0; c < BN; c++) {
            const __nv_bfloat16* ah = Ahi + (size_t)row * K;
            const __nv_bfloat16* al = Alo + (size_t)row * K;
            const __nv_bfloat16* bh = Bhi + (size_t)(bn + c) * K;
            const __nv_bfloat16* bl = Blo + (size_t)(bn + c) * K;
            float acc = 0.f;
            for (int kk = 0; kk < K; kk++)
                acc += (__bfloat162float(ah[kk]) + __bfloat162float(al[kk])) *
                       (__bfloat162float(bh[kk]) + __bfloat162float(bl[kk]));
            vals[c] = acc;
        }
        float mean = 0.f, rstd = 1.f;
        if (EPI >= 2) {
            float s = 0.f, s2 = 0.f;
            for (int c = 0; c < BN; c++) { s += vals[c]; s2 += vals[c] * vals[c]; }
            mean = s / BN;
            rstd = rsqrtf(s2 / BN - mean * mean + 1e-5f);
        }
        for (int c = 0; c < BN; c++) {
            float v = vals[c];
            if (EPI == 1) v = fmaxf(v, 0.f);
            if (EPI >= 2) { v = (v - mean) * rstd * Gw[c] + Bw[c]; if (EPI == 3) v *= 0.5f; }
            size_t ro = (size_t)row * ldc + bn + coff + c;
            if (EPI == 0)      Cf[ro] = v;
            else if (EPI == 3) Cf[ro] += v;
            else               split_store(Chi, Clo, ro, v);
        }
    }
#endif
}

// ---------------- coalesced permutes ----------------
__device__ __forceinline__ const float* sel3(const float* a, const float* b,
                                             const float* c, int z) {
    return z == 0 ? a : (z == 1 ? b : c);
}
__device__ __forceinline__ float* sel3m(float* a, float* b, float* c, int z) {
    return z == 0 ? a : (z == 1 ? b : c);
}

// mode 13: within-row shuffle dst[l,c] = src[l,(c&7)*32 + (c>>3)]
__global__ void __launch_bounds__(256) perm13(const float* q, const float* k, const float* v,
                                              float* qd, float* kd, float* vd) {
    __shared__ float s[8][256];
    const float* S = sel3(q, k, v, blockIdx.z);
    float* Dd = sel3m(qd, kd, vd, blockIdx.z);
    size_t rowbase = (size_t)blockIdx.x * 8;
    int t = threadIdx.x;
    #pragma unroll
    for (int i = 0; i < 8; i++) s[i][t] = S[(rowbase + i) * 256 + t];
    __syncthreads();
    int c0 = (t & 7) * 32 + (t >> 3);
    #pragma unroll
    for (int i = 0; i < 8; i++) Dd[(rowbase + i) * 256 + t] = s[i][c0];
}

// mode 21: dst[h0*153600 + l0*32 + dn] = src[l0*256 + h0*32 + dn]  (float4 copy)
__global__ void __launch_bounds__(256) perm21(const float4* q, const float4* k, const float4* v,
                                              float4* qd, float4* kd, float4* vd) {
    const float4* S = sel3((const float*)q, (const float*)k, (const float*)v, blockIdx.z)
                          ? (blockIdx.z == 0 ? q : (blockIdx.z == 1 ? k : v)) : q;
    float4* Dd = blockIdx.z == 0 ? qd : (blockIdx.z == 1 ? kd : vd);
    int b = blockIdx.y;
    int idx = blockIdx.x * 256 + threadIdx.x;      // 0 .. 307199
    int h0 = idx / 38400;
    int r2 = idx % 38400;
    int l0 = r2 >> 3, j = r2 & 7;
    size_t bo = (size_t)b * (LL * 64);
    Dd[bo + idx] = S[bo + (size_t)l0 * 64 + h0 * 8 + j];
}

// mode 32: dst[d0*38400 + h0*4800 + l0] = src[l0*256 + h0*32 + d0]  (32x32 tile transpose)
__global__ void __launch_bounds__(256) perm32(const float* q, const float* k, const float* v,
                                              float* qd, float* kd, float* vd) {
    __shared__ float sm[32][33];
    const float* S = sel3(q, k, v, blockIdx.z);
    float* Dd = sel3m(qd, kd, vd, blockIdx.z);
    int b = blockIdx.y;
    int l0b = blockIdx.x * 32;
    size_t bo = (size_t)b * BSTRIDE;
    int wr = threadIdx.x >> 5, lane = threadIdx.x & 31;
    for (int h0 = 0; h0 < H; h0++) {
        #pragma unroll
        for (int it = 0; it < 4; it++) {
            int row = wr + it * 8;
            sm[row][lane] = S[bo + (size_t)(l0b + row) * 256 + h0 * 32 + lane];
        }
        __syncthreads();
        #pragma unroll
        for (int it = 0; it < 4; it++) {
            int d0 = wr + it * 8;
            Dd[bo + (size_t)d0 * 38400 + h0 * 4800 + l0b + lane] = sm[lane][d0];
        }
        __syncthreads();
    }
}

// ---------------- KV reduce ----------------
#define KVSPLIT 10
#define KVCHUNK (LL/KVSPLIT)
__global__ void __launch_bounds__(256) kv_reduce(const float* __restrict__ k,
                                                 const float* __restrict__ v) {
    int b = blockIdx.x >> 3, h = blockIdx.x & 7;
    int sbeg = blockIdx.y * KVCHUNK;
    const float* kb = k + (size_t)b * BSTRIDE + h * DH;
    const float* vb = v + (size_t)b * BSTRIDE + h * DH;
    __shared__ float ks[8][32], vs[8][32];
    int t = threadIdx.x;
    int r = t >> 5, c = t & 31;
    float acc[4] = {0.f, 0.f, 0.f, 0.f};
    float ksacc = 0.f;
    for (int s0 = sbeg; s0 < sbeg + KVCHUNK; s0 += 8) {
        ks[r][c] = phi(kb[(size_t)(s0 + r) * D + c]);
        vs[r][c] = vb[(size_t)(s0 + r) * D + c];
        __syncthreads();
        #pragma unroll
        for (int row = 0; row < 8; row++) {
            float ve = vs[row][c];
            #pragma unroll
            for (int jj = 0; jj < 4; jj++)
                acc[jj] += ks[row][r + jj * 8] * ve;
        }
        if (t < 32) {
            #pragma unroll
            for (int row = 0; row < 8; row++) ksacc += ks[row][t];
        }
        __syncthreads();
    }
    float* kvout = g_kv + (size_t)(b * H + h) * DH * DH;
    #pragma unroll
    for (int jj = 0; jj < 4; jj++)
        atomicAdd(&kvout[(r + jj * 8) * DH + c], acc[jj]);
    if (t < 32) atomicAdd(&g_ksum[(b * H + h) * DH + t], ksacc);
}

// ---------------- attention apply (ATOK tokens/block, dynamic smem) ----------------
__global__ void __launch_bounds__(256) attn_out(const float* __restrict__ q,
                                                __nv_bfloat16* __restrict__ mhi,
                                                __nv_bfloat16* __restrict__ mlo) {
    extern __shared__ float as_[];
    float* sKV = as_;                       // 8192
    float* sKs = sKV + H * DH * DH;         // 256
    float (*sQ)[256] = (float(*)[256])(sKs + H * DH);  // ATOK*256
    float* sZ = (float*)(sQ + ATOK);        // ATOK*H
    int b  = blockIdx.y;
    int l0 = blockIdx.x * ATOK;
    int t = threadIdx.x;
    const float* kvb = g_kv + (size_t)b * H * DH * DH;
    #pragma unroll
    for (int i = t; i < H * DH * DH; i += 256) sKV[i] = kvb[i];
    if (t < H * DH) sKs[t] = g_ksum[b * H * DH + t];
    const float* qb = q + (size_t)b * BSTRIDE + (size_t)l0 * D;
    #pragma unroll
    for (int i = 0; i < ATOK; i++) sQ[i][t] = phi(qb[(size_t)i * D + t]);
    __syncthreads();
    {
        int tok = t >> 3, h = t & 7;       // 256 threads = 32 tok x 8 heads
        float z = 0.f;
        #pragma unroll
        for (int d = 0; d < DH; d++) z += sQ[tok][h * DH + d] * sKs[h * DH + d];
        sZ[tok * H + h] = 1.f / (z + 1e-6f);
    }
    __syncthreads();
    int c = t, h = c >> 5, e = c & 31;
    size_t base = (size_t)b * BSTRIDE + (size_t)l0 * D;
    #pragma unroll 4
    for (int jj = 0; jj < ATOK; jj++) {
        float dot = 0.f;
        #pragma unroll
        for (int d = 0; d < DH; d++)
            dot += sQ[jj][h * DH + d] * sKV[(h * DH + d) * DH + e];
        split_store(mhi, mlo, base + (size_t)jj * D + c, dot * sZ[jj * H + h]);
    }
}

__global__ void __launch_bounds__(256) copy4(const float4* __restrict__ src,
                                             float4* __restrict__ dst, int n) {
    int i = blockIdx.x * 256 + threadIdx.x;
    if (i < n) dst[i] = src[i];
}

// ---------------- host orchestration ----------------
extern "C" void kernel_launch(void* const* d_in, const int* in_sizes, int n_in,
                              void* d_out, int out_size) {
    (void)in_sizes; (void)n_in; (void)out_size;
    const float* x   = (const float*)d_in[0];
    const float* src = (const float*)d_in[1];
    const float* Wq  = (const float*)d_in[2];
    const float* Wk  = (const float*)d_in[3];
    const float* Wv  = (const float*)d_in[4];
    const float* Wm  = (const float*)d_in[5];
    const float* W1  = (const float*)d_in[6];
    const float* W2  = (const float*)d_in[7];
    const float* g1  = (const float*)d_in[8];
    const float* b1  = (const float*)d_in[9];
    const float* g2  = (const float*)d_in[10];
    const float* b2  = (const float*)d_in[11];
    float* out = (float*)d_out;

    float *q, *k, *v, *qp, *kp, *vp, *xmid, *kv, *ksum;
    cudaGetSymbolAddress((void**)&q,    g_q);
    cudaGetSymbolAddress((void**)&k,    g_k);
    cudaGetSymbolAddress((void**)&v,    g_v);
    cudaGetSymbolAddress((void**)&qp,   g_qp);
    cudaGetSymbolAddress((void**)&kp,   g_kp);
    cudaGetSymbolAddress((void**)&vp,   g_vp);
    cudaGetSymbolAddress((void**)&xmid, g_xmid);
    cudaGetSymbolAddress((void**)&kv,   g_kv);
    cudaGetSymbolAddress((void**)&ksum, g_ksum);

    __nv_bfloat16 *mhi, *mlo, *hhi, *hlo, *thi, *tlo;
    __nv_bfloat16 *wqh, *wql, *wkh, *wkl, *wvh, *wvl, *wmh, *wml, *w1h, *w1l, *w2h, *w2l;
    cudaGetSymbolAddress((void**)&mhi, g_mhi);  cudaGetSymbolAddress((void**)&mlo, g_mlo);
    cudaGetSymbolAddress((void**)&hhi, g_hhi);  cudaGetSymbolAddress((void**)&hlo, g_hlo);
    cudaGetSymbolAddress((void**)&thi, g_thi);  cudaGetSymbolAddress((void**)&tlo, g_tlo);
    cudaGetSymbolAddress((void**)&wqh, g_wqh);  cudaGetSymbolAddress((void**)&wql, g_wql);
    cudaGetSymbolAddress((void**)&wkh, g_wkh);  cudaGetSymbolAddress((void**)&wkl, g_wkl);
    cudaGetSymbolAddress((void**)&wvh, g_wvh);  cudaGetSymbolAddress((void**)&wvl, g_wvl);
    cudaGetSymbolAddress((void**)&wmh, g_wmh);  cudaGetSymbolAddress((void**)&wml, g_wml);
    cudaGetSymbolAddress((void**)&w1h, g_w1h);  cudaGetSymbolAddress((void**)&w1l, g_w1l);
    cudaGetSymbolAddress((void**)&w2h, g_w2h);  cudaGetSymbolAddress((void**)&w2l, g_w2l);

    cudaFuncSetAttribute(tc_gemm<0>, cudaFuncAttributeMaxDynamicSharedMemorySize, SMEM_DYN);
    cudaFuncSetAttribute(tc_gemm<1>, cudaFuncAttributeMaxDynamicSharedMemorySize, SMEM_DYN);
    cudaFuncSetAttribute(tc_gemm<2>, cudaFuncAttributeMaxDynamicSharedMemorySize, SMEM_DYN);
    cudaFuncSetAttribute(tc_gemm<3>, cudaFuncAttributeMaxDynamicSharedMemorySize, SMEM_DYN);
    const int ATTN_SMEM = (H*DH*DH + H*DH + ATOK*256 + ATOK*H) * 4;
    cudaFuncSetAttribute(attn_out, cudaFuncAttributeMaxDynamicSharedMemorySize, ATTN_SMEM);

    dim3 thr(256);

    // weights -> transposed bf16 hi/lo
    wconv<<<(D*D + 255)/256, thr>>>(Wq, wqh, wql, D, D);
    wconv<<<(D*D + 255)/256, thr>>>(Wk, wkh, wkl, D, D);
    wconv<<<(D*D + 255)/256, thr>>>(Wv, wvh, wvl, D, D);
    wconv<<<(D*D + 255)/256, thr>>>(Wm, wmh, wml, D, D);
    wconv<<<(4*D*D + 255)/256, thr>>>(W1, w1h, w1l, 2*D, 2*D);
    wconv<<<(2*D*D + 255)/256, thr>>>(W2, w2h, w2l, 2*D, D);

    // projections (EPI0, coalesced)
    aconv<<<ROWS*D/4/256, thr>>>((const float4*)x, (__nv_bfloat162*)mhi, (__nv_bfloat162*)mlo, ROWS*D/4);
    tc_gemm<0><<<dim3(1, ROWS/BM), thr, SMEM_DYN>>>(mhi, mlo, wqh, wql, q, nullptr, nullptr, nullptr, nullptr, D, D, D, 0);
    aconv<<<ROWS*D/4/256, thr>>>((const float4*)src, (__nv_bfloat162*)mhi, (__nv_bfloat162*)mlo, ROWS*D/4);
    tc_gemm<0><<<dim3(1, ROWS/BM), thr, SMEM_DYN>>>(mhi, mlo, wkh, wkl, k, nullptr, nullptr, nullptr, nullptr, D, D, D, 0);
    tc_gemm<0><<<dim3(1, ROWS/BM), thr, SMEM_DYN>>>(mhi, mlo, wvh, wvl, v, nullptr, nullptr, nullptr, nullptr, D, D, D, 0);

    copy4<<<ROWS*D/4/256, thr>>>((const float4*)x, (float4*)xmid, ROWS*D/4);
    hcat_base<<<ROWS*64/256, thr>>>((const float4*)x, hhi, hlo);

    auto block = [&](int mode, float* accbuf) {
        const float *qq = q, *kk = k, *vv = v;
        if (mode) {
            if (mode == 13) perm13<<<dim3(ROWS/8, 1, 3), thr>>>(q, k, v, qp, kp, vp);
            if (mode == 21) perm21<<<dim3(1200, BS, 3), thr>>>((const float4*)q, (const float4*)k, (const float4*)v,
                                                               (float4*)qp, (float4*)kp, (float4*)vp);
            if (mode == 32) perm32<<<dim3(150, BS, 3), thr>>>(q, k, v, qp, kp, vp);
            qq = qp; kk = kp; vv = vp;
        }
        cudaMemsetAsync(kv,   0, (size_t)BS*H*DH*DH*sizeof(float));
        cudaMemsetAsync(ksum, 0, (size_t)BS*H*DH*sizeof(float));
        kv_reduce<<<dim3(BS*H, KVSPLIT), thr>>>(kk, vv);
        attn_out<<<dim3(LL/ATOK, BS), thr, ATTN_SMEM>>>(qq, mhi, mlo);
        // Wm GEMM + LN(g1,b1) -> hcat LN-half
        tc_gemm<2><<<dim3(1, ROWS/BM), thr, SMEM_DYN>>>(mhi, mlo, wmh, wml,
                nullptr, hhi, hlo, g1, b1, D, D, 2*D, D);
        // W1 GEMM + relu -> thi/tlo
        tc_gemm<1><<<dim3(2, ROWS/BM), thr, SMEM_DYN>>>(hhi, hlo, w1h, w1l,
                nullptr, thi, tlo, nullptr, nullptr, 2*D, 2*D, 2*D, 0);
        // W2 GEMM + acc += 0.5*LN(g2,b2)
        tc_gemm<3><<<dim3(1, ROWS/BM), thr, SMEM_DYN>>>(thi, tlo, w2h, w2l,
                accbuf, nullptr, nullptr, g2, b2, 2*D, D, D, 0);
    };

    block(0,  xmid);
    block(13, xmid);
    copy4<<<ROWS*D/4/256, thr>>>((const float4*)xmid, (float4*)out, ROWS*D/4);
    hcat_base<<<ROWS*64/256, thr>>>((const float4*)xmid, hhi, hlo);
    block(21, out);
    block(32, out);
}

// round 5
// speedup vs baseline: 1.1159x; 1.1159x over previous
#include <cuda_runtime.h>
#include <cuda.h>
#include <cuda_bf16.h>
#include <math.h>
#include <stdint.h>

#if defined(__CUDA_ARCH__) && defined(__CUDA_ARCH_FEAT_SM103_ALL)
#define HAS_TCGEN05 1
#else
#define HAS_TCGEN05 0
#endif

#define BS 8
#define LL 4800
#define D 256
#define H 8
#define DH 32
#define ROWS (BS*LL)   // 38400
#define BSTRIDE (LL*D)

#define BM 128
#define BN 256
#define BK 64
#define A_HI 0
#define A_LO 16384
#define B_HI 32768
#define B_LO 65536
#define STAGE_BYTES 98304
#define SMEM_DYN (2*STAGE_BYTES + 1024)

#define ATOK 32

// ---------------- scratch (device globals) ----------------
__device__ float g_q   [BS*LL*D];
__device__ float g_k   [BS*LL*D];
__device__ float g_v   [BS*LL*D];
__device__ float g_qp  [BS*LL*D];
__device__ float g_kp  [BS*LL*D];
__device__ float g_vp  [BS*LL*D];
__device__ float g_xmid[BS*LL*D];
__device__ float g_kv  [BS*H*DH*DH];
__device__ float g_ksum[BS*H*DH];

// bf16 hi/lo buffers (TMA sources: align 1024)
__device__ __align__(1024) __nv_bfloat16 g_mhi[ROWS*D],   g_mlo[ROWS*D];
__device__ __align__(1024) __nv_bfloat16 g_hhi[ROWS*2*D], g_hlo[ROWS*2*D];
__device__ __align__(1024) __nv_bfloat16 g_thi[ROWS*2*D], g_tlo[ROWS*2*D];

// transposed bf16 weights [N,K]
__device__ __align__(1024) __nv_bfloat16 g_wqh[D*D],     g_wql[D*D];
__device__ __align__(1024) __nv_bfloat16 g_wkh[D*D],     g_wkl[D*D];
__device__ __align__(1024) __nv_bfloat16 g_wvh[D*D],     g_wvl[D*D];
__device__ __align__(1024) __nv_bfloat16 g_wmh[D*D],     g_wml[D*D];
__device__ __align__(1024) __nv_bfloat16 g_w1h[2*D*2*D], g_w1l[2*D*2*D];
__device__ __align__(1024) __nv_bfloat16 g_w2h[D*2*D],   g_w2l[D*2*D];

// ---------------- helpers ----------------
__device__ __forceinline__ float phi(float x) { return x > 0.f ? x + 1.f : __expf(x); }
__device__ __forceinline__ uint32_t smem_u32(const void* p) {
    uint32_t a;
    asm("{ .reg .u64 t; cvta.to.shared.u64 t, %1; cvt.u32.u64 %0, t; }" : "=r"(a) : "l"(p));
    return a;
}
__device__ __forceinline__ void split_store(__nv_bfloat16* hi, __nv_bfloat16* lo,
                                            size_t idx, float v) {
    __nv_bfloat16 h = __float2bfloat16(v);
    hi[idx] = h;
    lo[idx] = __float2bfloat16(v - __bfloat162float(h));
}

#if HAS_TCGEN05
__device__ __forceinline__ void mbar_init(uint32_t a, uint32_t cnt) {
    asm volatile("mbarrier.init.shared.b64 [%0], %1;" :: "r"(a), "r"(cnt) : "memory");
}
__device__ __forceinline__ void mbar_wait(uint32_t a, uint32_t parity) {
    asm volatile(
        "{\n\t.reg .pred P;\n"
        "W_%=:\n\t"
        "mbarrier.try_wait.parity.acquire.cta.shared::cta.b64 P, [%0], %1, 0x989680;\n\t"
        "@!P bra W_%=;\n\t}"
        :: "r"(a), "r"(parity) : "memory");
}
__device__ __forceinline__ void mbar_expect_tx(uint32_t a, uint32_t bytes) {
    asm volatile("mbarrier.arrive.expect_tx.shared.b64 _, [%0], %1;"
                 :: "r"(a), "r"(bytes) : "memory");
}
__device__ __forceinline__ void tma2d(uint32_t smem, const CUtensorMap* map,
                                      int x, int y, uint32_t mbar) {
    asm volatile(
        "cp.async.bulk.tensor.2d.shared::cta.global.tile.mbarrier::complete_tx::bytes "
        "[%0], [%1, {%2, %3}], [%4];"
        :: "r"(smem), "l"(map), "r"(x), "r"(y), "r"(mbar) : "memory");
}
__device__ __forceinline__ uint64_t make_desc(uint32_t addr) {
    const uint64_t base = (uint64_t(2) << 61) | (uint64_t(1) << 46)
                        | (uint64_t(64) << 32) | (uint64_t(1) << 16);
    return base | ((uint64_t)(addr >> 4) & 0x3FFF);
}
__device__ __forceinline__ void mma_f16_ss(uint32_t d, uint64_t a, uint64_t b,
                                           uint32_t idesc, uint32_t en) {
    asm volatile(
        "{\n\t.reg .pred p;\n\tsetp.ne.u32 p, %5, 0;\n\t"
        "tcgen05.mma.cta_group::1.kind::f16 [%0], %1, %2, %3, {%4, %4, %4, %4}, p;\n\t}"
        :: "r"(d), "l"(a), "l"(b), "r"(idesc), "r"(0u), "r"(en) : "memory");
}
__device__ __forceinline__ void tc_commit(uint32_t mbar) {
    asm volatile(
        "tcgen05.commit.cta_group::1.mbarrier::arrive::one.shared::cluster.b64 [%0];"
        :: "r"(mbar) : "memory");
}
__device__ __forceinline__ void ldtm32(uint32_t* r, uint32_t addr) {
    asm volatile(
        "tcgen05.ld.sync.aligned.32x32b.x32.b32 "
        "{%0, %1, %2, %3, %4, %5, %6, %7, "
        " %8, %9, %10, %11, %12, %13, %14, %15, "
        " %16, %17, %18, %19, %20, %21, %22, %23, "
        " %24, %25, %26, %27, %28, %29, %30, %31}, [%32];"
        : "=r"(r[0]),  "=r"(r[1]),  "=r"(r[2]),  "=r"(r[3]),
          "=r"(r[4]),  "=r"(r[5]),  "=r"(r[6]),  "=r"(r[7]),
          "=r"(r[8]),  "=r"(r[9]),  "=r"(r[10]), "=r"(r[11]),
          "=r"(r[12]), "=r"(r[13]), "=r"(r[14]), "=r"(r[15]),
          "=r"(r[16]), "=r"(r[17]), "=r"(r[18]), "=r"(r[19]),
          "=r"(r[20]), "=r"(r[21]), "=r"(r[22]), "=r"(r[23]),
          "=r"(r[24]), "=r"(r[25]), "=r"(r[26]), "=r"(r[27]),
          "=r"(r[28]), "=r"(r[29]), "=r"(r[30]), "=r"(r[31])
        : "r"(addr));
    asm volatile("tcgen05.wait::ld.sync.aligned;" ::: "memory");
}
#endif

// ---------------- convert kernels ----------------
__global__ void __launch_bounds__(256) aconv(const float4* __restrict__ a,
                                             __nv_bfloat162* __restrict__ hi,
                                             __nv_bfloat162* __restrict__ lo, int n4) {
    int i = blockIdx.x * 256 + threadIdx.x;
    if (i >= n4) return;
    float4 v = a[i];
    __nv_bfloat16 h0 = __float2bfloat16(v.x), h1 = __float2bfloat16(v.y);
    __nv_bfloat16 h2 = __float2bfloat16(v.z), h3 = __float2bfloat16(v.w);
    hi[2*i]   = __halves2bfloat162(h0, h1);
    hi[2*i+1] = __halves2bfloat162(h2, h3);
    lo[2*i]   = __halves2bfloat162(__float2bfloat16(v.x - __bfloat162float(h0)),
                                   __float2bfloat16(v.y - __bfloat162float(h1)));
    lo[2*i+1] = __halves2bfloat162(__float2bfloat16(v.z - __bfloat162float(h2)),
                                   __float2bfloat16(v.w - __bfloat162float(h3)));
}

__global__ void __launch_bounds__(256) wconv(const float* __restrict__ W,
                                             __nv_bfloat16* __restrict__ hi,
                                             __nv_bfloat16* __restrict__ lo,
                                             int K, int N) {
    int i = blockIdx.x * 256 + threadIdx.x;
    if (i >= N * K) return;
    int n = i / K, k = i % K;
    float v = W[(size_t)k * N + n];
    __nv_bfloat16 h = __float2bfloat16(v);
    hi[i] = h;
    lo[i] = __float2bfloat16(v - __bfloat162float(h));
}

// xb -> (copy to dst) + hcat base half (pitch 512)
__global__ void __launch_bounds__(256) prep_base(const float4* __restrict__ xb,
                                                 float4* __restrict__ dst,
                                                 __nv_bfloat16* __restrict__ hhi,
                                                 __nv_bfloat16* __restrict__ hlo) {
    int i = blockIdx.x * 256 + threadIdx.x;   // float4 index, ROWS*64 total
    if (i >= ROWS * 64) return;
    float4 v = xb[i];
    if (dst) dst[i] = v;
    int row = i >> 6, j = i & 63;
    size_t o = (size_t)row * 512 + j * 4;
    split_store(hhi, hlo, o + 0, v.x);
    split_store(hhi, hlo, o + 1, v.y);
    split_store(hhi, hlo, o + 2, v.z);
    split_store(hhi, hlo, o + 3, v.w);
}

// ---------------- tcgen05 GEMM with TMA mainloop ----------------
// EPI 0: fp32 -> Cf ; EPI 1: relu -> bf16 hi/lo ; EPI 2: LN -> bf16 hi/lo at coff ;
// EPI 3: Cf += 0.5*LN
template<int EPI>
__global__ void __launch_bounds__(256, 1) tc_gemm(
        const __grid_constant__ CUtensorMap mAh, const __grid_constant__ CUtensorMap mAl,
        const __grid_constant__ CUtensorMap mBh, const __grid_constant__ CUtensorMap mBl,
        const __nv_bfloat16* __restrict__ Ahi, const __nv_bfloat16* __restrict__ Alo,
        const __nv_bfloat16* __restrict__ Bhi, const __nv_bfloat16* __restrict__ Blo,
        float* __restrict__ Cf,
        __nv_bfloat16* __restrict__ Chi, __nv_bfloat16* __restrict__ Clo,
        const float* __restrict__ Gw, const float* __restrict__ Bw,
        int K, int N, int ldc, int coff) {
#if HAS_TCGEN05
    extern __shared__ char dsm_raw[];
    char* sbase = (char*)(((uintptr_t)dsm_raw + 1023) & ~(uintptr_t)1023);
    __shared__ uint32_t s_tmem;
    __shared__ __align__(8) unsigned long long s_mbar[4];  // full0 full1 mma0 mma1
    const uint32_t mb = smem_u32(s_mbar);
    const int t = threadIdx.x, wid = t >> 5, lane = t & 31;

    if (wid == 0) {
        asm volatile("tcgen05.alloc.cta_group::1.sync.aligned.shared::cta.b32 [%0], %1;"
                     :: "r"(smem_u32(&s_tmem)), "r"(256u) : "memory");
        asm volatile("tcgen05.relinquish_alloc_permit.cta_group::1.sync.aligned;");
    }
    if (t == 0) {
        mbar_init(mb, 1); mbar_init(mb + 8, 1);
        mbar_init(mb + 16, 1); mbar_init(mb + 24, 1);
    }
    __syncthreads();
    const uint32_t tmem = s_tmem;

    const int bm = blockIdx.y * BM, bn = blockIdx.x * BN;
    const int NC = K >> 6;
    const uint32_t idesc = (1u << 4) | (1u << 7) | (1u << 10)
                         | ((BN / 8) << 17) | ((BM / 16) << 24);
    const uint32_t sb32 = smem_u32(sbase);

    if (t == 0) {
        // prologue: fill both stages
        mbar_expect_tx(mb, STAGE_BYTES);
        tma2d(sb32 + A_HI, &mAh, 0, bm, mb);
        tma2d(sb32 + A_LO, &mAl, 0, bm, mb);
        tma2d(sb32 + B_HI, &mBh, 0, bn, mb);
        tma2d(sb32 + B_LO, &mBl, 0, bn, mb);
        if (NC > 1) {
            uint32_t st = sb32 + STAGE_BYTES;
            mbar_expect_tx(mb + 8, STAGE_BYTES);
            tma2d(st + A_HI, &mAh, BK, bm, mb + 8);
            tma2d(st + A_LO, &mAl, BK, bm, mb + 8);
            tma2d(st + B_HI, &mBh, BK, bn, mb + 8);
            tma2d(st + B_LO, &mBl, BK, bn, mb + 8);
        }
        int fph[2] = {0, 0}, mph[2] = {0, 0}, pend[2] = {0, 0};
        for (int c = 0; c < NC; c++) {
            const int s = c & 1;
            mbar_wait(mb + s * 8, fph[s]); fph[s] ^= 1;
            uint32_t st = sb32 + s * STAGE_BYTES;
            uint64_t dAh = make_desc(st + A_HI), dAl = make_desc(st + A_LO);
            uint64_t dBh = make_desc(st + B_HI), dBl = make_desc(st + B_LO);
            #pragma unroll
            for (int k = 0; k < 4; k++) {
                mma_f16_ss(tmem, dAh + k * 2, dBh + k * 2, idesc, !(c == 0 && k == 0));
                mma_f16_ss(tmem, dAh + k * 2, dBl + k * 2, idesc, 1u);
                mma_f16_ss(tmem, dAl + k * 2, dBh + k * 2, idesc, 1u);
            }
            tc_commit(mb + 16 + s * 8);
            pend[s] = 1;
            if (c + 2 < NC) {
                mbar_wait(mb + 16 + s * 8, mph[s]); mph[s] ^= 1; pend[s] = 0;
                int k0 = (c + 2) * BK;
                mbar_expect_tx(mb + s * 8, STAGE_BYTES);
                tma2d(st + A_HI, &mAh, k0, bm, mb + s * 8);
                tma2d(st + A_LO, &mAl, k0, bm, mb + s * 8);
                tma2d(st + B_HI, &mBh, k0, bn, mb + s * 8);
                tma2d(st + B_LO, &mBl, k0, bn, mb + s * 8);
            }
        }
        if (pend[0]) mbar_wait(mb + 16, mph[0]);
        if (pend[1]) mbar_wait(mb + 24, mph[1]);
    }
    __syncthreads();
    asm volatile("tcgen05.fence::after_thread_sync;" ::: "memory");

    // epilogue: smem-staged coalesced stores
    float (*tile)[33] = (float(*)[33])sbase;
    float mean = 0.f, rstd = 0.f;
    if (EPI >= 2 && wid < 4) {
        float s = 0.f, s2 = 0.f;
        #pragma unroll
        for (int ch = 0; ch < 8; ch++) {
            uint32_t r[32];
            ldtm32(r, tmem + ch * 32);
            #pragma unroll
            for (int j = 0; j < 32; j++) {
                float v = __uint_as_float(r[j]);
                s += v; s2 += v * v;
            }
        }
        mean = s * (1.f / 256.f);
        float var = fmaf(-mean, mean, s2 * (1.f / 256.f));
        rstd = rsqrtf(var + 1e-5f);
    }
    #pragma unroll
    for (int ch = 0; ch < 8; ch++) {
        if (wid < 4) {
            uint32_t r[32];
            ldtm32(r, tmem + ch * 32);
            int rloc = wid * 32 + lane;
            #pragma unroll
            for (int j = 0; j < 32; j++) {
                float v = __uint_as_float(r[j]);
                if (EPI == 1) v = fmaxf(v, 0.f);
                if (EPI >= 2) {
                    int col = ch * 32 + j;
                    v = (v - mean) * rstd * Gw[col] + Bw[col];
                    if (EPI == 3) v *= 0.5f;
                }
                tile[rloc][j] = v;
            }
        }
        __syncthreads();
        #pragma unroll
        for (int i = 0; i < 16; i++) {
            int idx = i * 256 + t;
            int rr = idx >> 5, cc = idx & 31;
            float v = tile[rr][cc];
            size_t ro = (size_t)(bm + rr) * ldc + bn + coff + ch * 32 + cc;
            if (EPI == 0)       Cf[ro] = v;
            else if (EPI == 3)  Cf[ro] += v;
            else                split_store(Chi, Clo, ro, v);
        }
        __syncthreads();
    }
    if (wid == 0)
        asm volatile("tcgen05.dealloc.cta_group::1.sync.aligned.b32 %0, %1;"
                     :: "r"(tmem), "r"(256u));
#else
    // compile-only fallback (never runs on GB300)
    const int bm = blockIdx.y * BM, bn = blockIdx.x * BN;
    const int t = threadIdx.x;
    if (t < BM) {
        int row = bm + t;
        float vals[BN];
        for (int c = 0; c < BN; c++) {
            const __nv_bfloat16* ah = Ahi + (size_t)row * K;
            const __nv_bfloat16* al = Alo + (size_t)row * K;
            const __nv_bfloat16* bh = Bhi + (size_t)(bn + c) * K;
            const __nv_bfloat16* bl = Blo + (size_t)(bn + c) * K;
            float acc = 0.f;
            for (int kk = 0; kk < K; kk++)
                acc += (__bfloat162float(ah[kk]) + __bfloat162float(al[kk])) *
                       (__bfloat162float(bh[kk]) + __bfloat162float(bl[kk]));
            vals[c] = acc;
        }
        float mean = 0.f, rstd = 1.f;
        if (EPI >= 2) {
            float s = 0.f, s2 = 0.f;
            for (int c = 0; c < BN; c++) { s += vals[c]; s2 += vals[c] * vals[c]; }
            mean = s / BN;
            rstd = rsqrtf(s2 / BN - mean * mean + 1e-5f);
        }
        for (int c = 0; c < BN; c++) {
            float v = vals[c];
            if (EPI == 1) v = fmaxf(v, 0.f);
            if (EPI >= 2) { v = (v - mean) * rstd * Gw[c] + Bw[c]; if (EPI == 3) v *= 0.5f; }
            size_t ro = (size_t)row * ldc + bn + coff + c;
            if (EPI == 0)      Cf[ro] = v;
            else if (EPI == 3) Cf[ro] += v;
            else               split_store(Chi, Clo, ro, v);
        }
    }
#endif
}

// ---------------- coalesced permutes ----------------
__global__ void __launch_bounds__(256) perm13(const float* q, const float* k, const float* v,
                                              float* qd, float* kd, float* vd) {
    __shared__ float s[8][256];
    const float* S = blockIdx.z == 0 ? q : (blockIdx.z == 1 ? k : v);
    float* Dd = blockIdx.z == 0 ? qd : (blockIdx.z == 1 ? kd : vd);
    size_t rowbase = (size_t)blockIdx.x * 8;
    int t = threadIdx.x;
    #pragma unroll
    for (int i = 0; i < 8; i++) s[i][t] = S[(rowbase + i) * 256 + t];
    __syncthreads();
    int c0 = (t & 7) * 32 + (t >> 3);
    #pragma unroll
    for (int i = 0; i < 8; i++) Dd[(rowbase + i) * 256 + t] = s[i][c0];
}

__global__ void __launch_bounds__(256) perm21(const float4* q, const float4* k, const float4* v,
                                              float4* qd, float4* kd, float4* vd) {
    const float4* S = blockIdx.z == 0 ? q : (blockIdx.z == 1 ? k : v);
    float4* Dd = blockIdx.z == 0 ? qd : (blockIdx.z == 1 ? kd : vd);
    int b = blockIdx.y;
    int idx = blockIdx.x * 256 + threadIdx.x;      // 0 .. 307199
    int h0 = idx / 38400;
    int r2 = idx % 38400;
    int l0 = r2 >> 3, j = r2 & 7;
    size_t bo = (size_t)b * (LL * 64);
    Dd[bo + idx] = S[bo + (size_t)l0 * 64 + h0 * 8 + j];
}

__global__ void __launch_bounds__(256) perm32(const float* q, const float* k, const float* v,
                                              float* qd, float* kd, float* vd) {
    __shared__ float sm[32][33];
    const float* S = blockIdx.z == 0 ? q : (blockIdx.z == 1 ? k : v);
    float* Dd = blockIdx.z == 0 ? qd : (blockIdx.z == 1 ? kd : vd);
    int b = blockIdx.y;
    int l0b = blockIdx.x * 32;
    size_t bo = (size_t)b * BSTRIDE;
    int wr = threadIdx.x >> 5, lane = threadIdx.x & 31;
    for (int h0 = 0; h0 < H; h0++) {
        #pragma unroll
        for (int it = 0; it < 4; it++) {
            int row = wr + it * 8;
            sm[row][lane] = S[bo + (size_t)(l0b + row) * 256 + h0 * 32 + lane];
        }
        __syncthreads();
        #pragma unroll
        for (int it = 0; it < 4; it++) {
            int d0 = wr + it * 8;
            Dd[bo + (size_t)d0 * 38400 + h0 * 4800 + l0b + lane] = sm[lane][d0];
        }
        __syncthreads();
    }
}

// ---------------- KV reduce ----------------
#define KVSPLIT 10
#define KVCHUNK (LL/KVSPLIT)
__global__ void __launch_bounds__(256) kv_reduce(const float* __restrict__ k,
                                                 const float* __restrict__ v) {
    int b = blockIdx.x >> 3, h = blockIdx.x & 7;
    int sbeg = blockIdx.y * KVCHUNK;
    const float* kb = k + (size_t)b * BSTRIDE + h * DH;
    const float* vb = v + (size_t)b * BSTRIDE + h * DH;
    __shared__ float ks[8][32], vs[8][32];
    int t = threadIdx.x;
    int r = t >> 5, c = t & 31;
    float acc[4] = {0.f, 0.f, 0.f, 0.f};
    float ksacc = 0.f;
    for (int s0 = sbeg; s0 < sbeg + KVCHUNK; s0 += 8) {
        ks[r][c] = phi(kb[(size_t)(s0 + r) * D + c]);
        vs[r][c] = vb[(size_t)(s0 + r) * D + c];
        __syncthreads();
        #pragma unroll
        for (int row = 0; row < 8; row++) {
            float ve = vs[row][c];
            #pragma unroll
            for (int jj = 0; jj < 4; jj++)
                acc[jj] += ks[row][r + jj * 8] * ve;
        }
        if (t < 32) {
            #pragma unroll
            for (int row = 0; row < 8; row++) ksacc += ks[row][t];
        }
        __syncthreads();
    }
    float* kvout = g_kv + (size_t)(b * H + h) * DH * DH;
    #pragma unroll
    for (int jj = 0; jj < 4; jj++)
        atomicAdd(&kvout[(r + jj * 8) * DH + c], acc[jj]);
    if (t < 32) atomicAdd(&g_ksum[(b * H + h) * DH + t], ksacc);
}

// ---------------- attention apply ----------------
__global__ void __launch_bounds__(256) attn_out(const float* __restrict__ q,
                                                __nv_bfloat16* __restrict__ mhi,
                                                __nv_bfloat16* __restrict__ mlo) {
    extern __shared__ float as_[];
    float* sKV = as_;
    float* sKs = sKV + H * DH * DH;
    float (*sQ)[256] = (float(*)[256])(sKs + H * DH);
    float* sZ = (float*)(sQ + ATOK);
    int b  = blockIdx.y;
    int l0 = blockIdx.x * ATOK;
    int t = threadIdx.x;
    const float* kvb = g_kv + (size_t)b * H * DH * DH;
    #pragma unroll
    for (int i = t; i < H * DH * DH; i += 256) sKV[i] = kvb[i];
    if (t < H * DH) sKs[t] = g_ksum[b * H * DH + t];
    const float* qb = q + (size_t)b * BSTRIDE + (size_t)l0 * D;
    #pragma unroll
    for (int i = 0; i < ATOK; i++) sQ[i][t] = phi(qb[(size_t)i * D + t]);
    __syncthreads();
    {
        int tok = t >> 3, h = t & 7;
        float z = 0.f;
        #pragma unroll
        for (int d = 0; d < DH; d++) z += sQ[tok][h * DH + d] * sKs[h * DH + d];
        sZ[tok * H + h] = 1.f / (z + 1e-6f);
    }
    __syncthreads();
    int c = t, h = c >> 5, e = c & 31;
    size_t base = (size_t)b * BSTRIDE + (size_t)l0 * D;
    #pragma unroll 4
    for (int jj = 0; jj < ATOK; jj++) {
        float dot = 0.f;
        #pragma unroll
        for (int d = 0; d < DH; d++)
            dot += sQ[jj][h * DH + d] * sKV[(h * DH + d) * DH + e];
        split_store(mhi, mlo, base + (size_t)jj * D + c, dot * sZ[jj * H + h]);
    }
}

// ---------------- host orchestration ----------------
typedef CUresult (*EncFn)(CUtensorMap*, CUtensorMapDataType, cuuint32_t, void*,
        const cuuint64_t*, const cuuint64_t*, const cuuint32_t*, const cuuint32_t*,
        CUtensorMapInterleave, CUtensorMapSwizzle, CUtensorMapL2promotion,
        CUtensorMapFloatOOBfill);

extern "C" void kernel_launch(void* const* d_in, const int* in_sizes, int n_in,
                              void* d_out, int out_size) {
    (void)in_sizes; (void)n_in; (void)out_size;
    const float* x   = (const float*)d_in[0];
    const float* src = (const float*)d_in[1];
    const float* Wq  = (const float*)d_in[2];
    const float* Wk  = (const float*)d_in[3];
    const float* Wv  = (const float*)d_in[4];
    const float* Wm  = (const float*)d_in[5];
    const float* W1  = (const float*)d_in[6];
    const float* W2  = (const float*)d_in[7];
    const float* g1  = (const float*)d_in[8];
    const float* b1  = (const float*)d_in[9];
    const float* g2  = (const float*)d_in[10];
    const float* b2  = (const float*)d_in[11];
    float* out = (float*)d_out;

    float *q, *k, *v, *qp, *kp, *vp, *xmid, *kv, *ksum;
    cudaGetSymbolAddress((void**)&q,    g_q);
    cudaGetSymbolAddress((void**)&k,    g_k);
    cudaGetSymbolAddress((void**)&v,    g_v);
    cudaGetSymbolAddress((void**)&qp,   g_qp);
    cudaGetSymbolAddress((void**)&kp,   g_kp);
    cudaGetSymbolAddress((void**)&vp,   g_vp);
    cudaGetSymbolAddress((void**)&xmid, g_xmid);
    cudaGetSymbolAddress((void**)&kv,   g_kv);
    cudaGetSymbolAddress((void**)&ksum, g_ksum);

    __nv_bfloat16 *mhi, *mlo, *hhi, *hlo, *thi, *tlo;
    __nv_bfloat16 *wqh, *wql, *wkh, *wkl, *wvh, *wvl, *wmh, *wml, *w1h, *w1l, *w2h, *w2l;
    cudaGetSymbolAddress((void**)&mhi, g_mhi);  cudaGetSymbolAddress((void**)&mlo, g_mlo);
    cudaGetSymbolAddress((void**)&hhi, g_hhi);  cudaGetSymbolAddress((void**)&hlo, g_hlo);
    cudaGetSymbolAddress((void**)&thi, g_thi);  cudaGetSymbolAddress((void**)&tlo, g_tlo);
    cudaGetSymbolAddress((void**)&wqh, g_wqh);  cudaGetSymbolAddress((void**)&wql, g_wql);
    cudaGetSymbolAddress((void**)&wkh, g_wkh);  cudaGetSymbolAddress((void**)&wkl, g_wkl);
    cudaGetSymbolAddress((void**)&wvh, g_wvh);  cudaGetSymbolAddress((void**)&wvl, g_wvl);
    cudaGetSymbolAddress((void**)&wmh, g_wmh);  cudaGetSymbolAddress((void**)&wml, g_wml);
    cudaGetSymbolAddress((void**)&w1h, g_w1h);  cudaGetSymbolAddress((void**)&w1l, g_w1l);
    cudaGetSymbolAddress((void**)&w2h, g_w2h);  cudaGetSymbolAddress((void**)&w2l, g_w2l);

    // tensormap encode via runtime-loaded driver entry point
    EncFn enc = nullptr;
    {
        void* fp = nullptr;
#if CUDART_VERSION >= 12050
        cudaDriverEntryPointQueryResult qr;
        cudaGetDriverEntryPoint("cuTensorMapEncodeTiled", &fp, cudaEnableDefault, &qr);
#else
        cudaGetDriverEntryPoint("cuTensorMapEncodeTiled", &fp, cudaEnableDefault);
#endif
        enc = (EncFn)fp;
    }
    auto mk = [&](void* ptr, uint64_t k_elems, uint64_t rows, uint32_t boxrows) {
        CUtensorMap m{};
        cuuint64_t dims[2] = {k_elems, rows};
        cuuint64_t strides[1] = {k_elems * 2};
        cuuint32_t box[2] = {64, boxrows};
        cuuint32_t es[2] = {1, 1};
        enc(&m, CU_TENSOR_MAP_DATA_TYPE_BFLOAT16, 2, ptr, dims, strides, box, es,
            CU_TENSOR_MAP_INTERLEAVE_NONE, CU_TENSOR_MAP_SWIZZLE_128B,
            CU_TENSOR_MAP_L2_PROMOTION_L2_128B, CU_TENSOR_MAP_FLOAT_OOB_FILL_NONE);
        return m;
    };
    // A maps (box 64x128)
    CUtensorMap tm_mhi = mk(mhi, 256, ROWS, 128), tm_mlo = mk(mlo, 256, ROWS, 128);
    CUtensorMap tm_hhi = mk(hhi, 512, ROWS, 128), tm_hlo = mk(hlo, 512, ROWS, 128);
    CUtensorMap tm_thi = mk(thi, 512, ROWS, 128), tm_tlo = mk(tlo, 512, ROWS, 128);
    // B maps (box 64x256)
    CUtensorMap tm_wqh = mk(wqh, 256, 256, 256), tm_wql = mk(wql, 256, 256, 256);
    CUtensorMap tm_wkh = mk(wkh, 256, 256, 256), tm_wkl = mk(wkl, 256, 256, 256);
    CUtensorMap tm_wvh = mk(wvh, 256, 256, 256), tm_wvl = mk(wvl, 256, 256, 256);
    CUtensorMap tm_wmh = mk(wmh, 256, 256, 256), tm_wml = mk(wml, 256, 256, 256);
    CUtensorMap tm_w1h = mk(w1h, 512, 512, 256), tm_w1l = mk(w1l, 512, 512, 256);
    CUtensorMap tm_w2h = mk(w2h, 512, 256, 256), tm_w2l = mk(w2l, 512, 256, 256);

    cudaFuncSetAttribute(tc_gemm<0>, cudaFuncAttributeMaxDynamicSharedMemorySize, SMEM_DYN);
    cudaFuncSetAttribute(tc_gemm<1>, cudaFuncAttributeMaxDynamicSharedMemorySize, SMEM_DYN);
    cudaFuncSetAttribute(tc_gemm<2>, cudaFuncAttributeMaxDynamicSharedMemorySize, SMEM_DYN);
    cudaFuncSetAttribute(tc_gemm<3>, cudaFuncAttributeMaxDynamicSharedMemorySize, SMEM_DYN);
    const int ATTN_SMEM = (H*DH*DH + H*DH + ATOK*256 + ATOK*H) * 4;
    cudaFuncSetAttribute(attn_out, cudaFuncAttributeMaxDynamicSharedMemorySize, ATTN_SMEM);

    dim3 thr(256);

    // weights -> transposed bf16 hi/lo
    wconv<<<(D*D + 255)/256, thr>>>(Wq, wqh, wql, D, D);
    wconv<<<(D*D + 255)/256, thr>>>(Wk, wkh, wkl, D, D);
    wconv<<<(D*D + 255)/256, thr>>>(Wv, wvh, wvl, D, D);
    wconv<<<(D*D + 255)/256, thr>>>(Wm, wmh, wml, D, D);
    wconv<<<(4*D*D + 255)/256, thr>>>(W1, w1h, w1l, 2*D, 2*D);
    wconv<<<(2*D*D + 255)/256, thr>>>(W2, w2h, w2l, 2*D, D);

    // projections
    aconv<<<ROWS*D/4/256, thr>>>((const float4*)x, (__nv_bfloat162*)mhi, (__nv_bfloat162*)mlo, ROWS*D/4);
    tc_gemm<0><<<dim3(1, ROWS/BM), thr, SMEM_DYN>>>(tm_mhi, tm_mlo, tm_wqh, tm_wql,
            mhi, mlo, wqh, wql, q, nullptr, nullptr, nullptr, nullptr, D, D, D, 0);
    aconv<<<ROWS*D/4/256, thr>>>((const float4*)src, (__nv_bfloat162*)mhi, (__nv_bfloat162*)mlo, ROWS*D/4);
    tc_gemm<0><<<dim3(1, ROWS/BM), thr, SMEM_DYN>>>(tm_mhi, tm_mlo, tm_wkh, tm_wkl,
            mhi, mlo, wkh, wkl, k, nullptr, nullptr, nullptr, nullptr, D, D, D, 0);
    tc_gemm<0><<<dim3(1, ROWS/BM), thr, SMEM_DYN>>>(tm_mhi, tm_mlo, tm_wvh, tm_wvl,
            mhi, mlo, wvh, wvl, v, nullptr, nullptr, nullptr, nullptr, D, D, D, 0);

    prep_base<<<ROWS*64/256, thr>>>((const float4*)x, (float4*)xmid, hhi, hlo);

    auto block = [&](int mode, float* accbuf) {
        const float *qq = q, *kk = k, *vv = v;
        if (mode) {
            if (mode == 13) perm13<<<dim3(ROWS/8, 1, 3), thr>>>(q, k, v, qp, kp, vp);
            if (mode == 21) perm21<<<dim3(1200, BS, 3), thr>>>((const float4*)q, (const float4*)k, (const float4*)v,
                                                               (float4*)qp, (float4*)kp, (float4*)vp);
            if (mode == 32) perm32<<<dim3(150, BS, 3), thr>>>(q, k, v, qp, kp, vp);
            qq = qp; kk = kp; vv = vp;
        }
        cudaMemsetAsync(kv,   0, (size_t)BS*H*DH*DH*sizeof(float));
        cudaMemsetAsync(ksum, 0, (size_t)BS*H*DH*sizeof(float));
        kv_reduce<<<dim3(BS*H, KVSPLIT), thr>>>(kk, vv);
        attn_out<<<dim3(LL/ATOK, BS), thr, ATTN_SMEM>>>(qq, mhi, mlo);
        tc_gemm<2><<<dim3(1, ROWS/BM), thr, SMEM_DYN>>>(tm_mhi, tm_mlo, tm_wmh, tm_wml,
                mhi, mlo, wmh, wml, nullptr, hhi, hlo, g1, b1, D, D, 2*D, D);
        tc_gemm<1><<<dim3(2, ROWS/BM), thr, SMEM_DYN>>>(tm_hhi, tm_hlo, tm_w1h, tm_w1l,
                hhi, hlo, w1h, w1l, nullptr, thi, tlo, nullptr, nullptr, 2*D, 2*D, 2*D, 0);
        tc_gemm<3><<<dim3(1, ROWS/BM), thr, SMEM_DYN>>>(tm_thi, tm_tlo, tm_w2h, tm_w2l,
                thi, tlo, w2h, w2l, accbuf, nullptr, nullptr, g2, b2, 2*D, D, D, 0);
    };

    block(0,  xmid);
    block(13, xmid);
    prep_base<<<ROWS*64/256, thr>>>((const float4*)xmid, (float4*)out, hhi, hlo);
    block(21, out);
    block(32, out);
}